// round 14
// baseline (speedup 1.0000x reference)
#include <cuda_runtime.h>
#include <cstdint>
#include <cstddef>

#define F_IN  128
#define F_HID 64
#define F_OUT 40
#define MAXN  100032
#define MAXE  1600000
#define SCAN_B 512
#define MAXNB  256   // max scan blocks (N <= 131072)

// ---------------- scratch (no allocation allowed) ----------------
__device__ __align__(256) float g_h1[(size_t)MAXN * F_HID];   // x @ W1^T (UNscaled)
__device__ __align__(256) float g_agg1[(size_t)MAXN * F_HID]; // layer-1 aggregate
__device__ __align__(256) float g_h3[(size_t)MAXN * F_OUT];   // dis .* (relu(agg1+b1) @ W2^T)
__device__ float g_dis[MAXN];
__device__ int   g_cnt[MAXN];       // zero-init at load; re-zeroed by agg2 for next replay
__device__ int   g_rowptr[MAXN + 1];
__device__ int   g_cursor[MAXN];
__device__ int   g_blocksum[MAXNB];
__device__ __align__(16) int2 g_perm2[MAXE];  // (src row, bits(dis[src]))

// ---------------- packed f32x2 helpers ----------------
__device__ __forceinline__ void ffma2(unsigned long long& d, unsigned long long a,
                                      unsigned long long b) {
    asm("fma.rn.f32x2 %0, %1, %2, %0;" : "+l"(d) : "l"(a), "l"(b));
}
__device__ __forceinline__ void unpack2(unsigned long long v, float& x, float& y) {
    asm("mov.b64 {%0, %1}, %2;" : "=f"(x), "=f"(y) : "l"(v));
}

// ---------------- edge helpers ----------------
__device__ __forceinline__ void count_one(int c, int N) {
    if ((unsigned)c < (unsigned)N) atomicAdd(&g_cnt[c], 1);
}
__device__ __forceinline__ void fill_one(int r, int c, int N) {
    if ((unsigned)r < (unsigned)N && (unsigned)c < (unsigned)N) {
        int pos = atomicAdd(&g_cursor[c], 1);
        if ((unsigned)pos < (unsigned)MAXE)
            g_perm2[pos] = make_int2(r, __float_as_int(g_dis[r]));
    }
}

// ---------------- K1/K4: GEMM1 half + edge phase (count or fill) -------------
// Blocks [0, nRowBlocks): 128 rows x 64 cols of h1 = x @ W1^T (unscaled).
// Blocks [nRowBlocks, ...): edge work. mode 0 = degree count, 1 = CSR fill.
__global__ __launch_bounds__(256) void gemm1_fused(const float* __restrict__ x,
                                                   const float* __restrict__ W1, int N,
                                                   int rowBlockStart, int nRowBlocks,
                                                   const int* __restrict__ ei, int E,
                                                   int mode, int vecOK) {
    __shared__ float2 xs2[32][65];   // [kk][rowpair]
    __shared__ float2 wd[32][65];    // [kk][j] duplicated (w,w)

    if ((int)blockIdx.x >= nRowBlocks) {
        // ----- edge phase -----
        int b = blockIdx.x - nRowBlocks;
        if (vecOK) {
            int t4 = E >> 2;
            int idx = b * 256 + threadIdx.x;
            if (idx < t4) {
                const int4* col4 = (const int4*)(ei + E);
                int4 c = __ldg(&col4[idx]);
                if (mode == 0) {
                    count_one(c.x, N); count_one(c.y, N);
                    count_one(c.z, N); count_one(c.w, N);
                } else {
                    const int4* row4 = (const int4*)ei;
                    int4 r = __ldg(&row4[idx]);
                    fill_one(r.x, c.x, N); fill_one(r.y, c.y, N);
                    fill_one(r.z, c.z, N); fill_one(r.w, c.w, N);
                }
            }
            if (b == 0 && threadIdx.x == 0) {           // tail (E % 4)
                for (int e = t4 * 4; e < E; e++) {
                    if (mode == 0) count_one(ei[(size_t)E + e], N);
                    else           fill_one(ei[e], ei[(size_t)E + e], N);
                }
            }
        } else {
            int e = b * 256 + threadIdx.x;
            if (e < E) {
                if (mode == 0) count_one(ei[(size_t)E + e], N);
                else           fill_one(ei[e], ei[(size_t)E + e], N);
            }
        }
        return;
    }

    // ----- GEMM phase -----
    int tid = threadIdx.x;
    int tx = tid & 15;
    int ty = tid >> 4;
    int rbase = (rowBlockStart + blockIdx.x) * 128;

    unsigned long long acc[4][4];
#pragma unroll
    for (int r = 0; r < 4; r++)
#pragma unroll
        for (int c = 0; c < 4; c++) acc[r][c] = 0ull;

#pragma unroll 1
    for (int kp = 0; kp < 4; kp++) {
        __syncthreads();
#pragma unroll
        for (int it = 0; it < 16; it++) {
            int idx = it * 256 + tid;
            int rr = idx >> 5, kk = idx & 31;
            int gr = rbase + rr;
            float v = (gr < N) ? x[(size_t)gr * F_IN + kp * 32 + kk] : 0.f;
            ((float*)&xs2[kk][rr >> 1])[rr & 1] = v;
        }
#pragma unroll
        for (int it = 0; it < 8; it++) {
            int idx = it * 256 + tid;
            int j = idx >> 5, kk = idx & 31;
            float v = W1[j * F_IN + kp * 32 + kk];
            wd[kk][j] = make_float2(v, v);
        }
        __syncthreads();

#pragma unroll
        for (int kk = 0; kk < 32; kk++) {
            unsigned long long xp[4], wv[4];
#pragma unroll
            for (int r = 0; r < 4; r++)
                xp[r] = *(const unsigned long long*)&xs2[kk][4 * ty + r];
#pragma unroll
            for (int c = 0; c < 4; c++)
                wv[c] = *(const unsigned long long*)&wd[kk][4 * tx + c];
#pragma unroll
            for (int r = 0; r < 4; r++)
#pragma unroll
                for (int c = 0; c < 4; c++) ffma2(acc[r][c], xp[r], wv[c]);
        }
    }

#pragma unroll
    for (int r = 0; r < 4; r++) {
        int row0 = rbase + 2 * (4 * ty + r);
        if (row0 >= N) break;
        float lo[4], hi[4];
#pragma unroll
        for (int c = 0; c < 4; c++) unpack2(acc[r][c], lo[c], hi[c]);
        *(float4*)&g_h1[(size_t)row0 * F_HID + 4 * tx] =
            make_float4(lo[0], lo[1], lo[2], lo[3]);
        if (row0 + 1 < N)
            *(float4*)&g_h1[(size_t)(row0 + 1) * F_HID + 4 * tx] =
                make_float4(hi[0], hi[1], hi[2], hi[3]);
    }
}

// ---------------- K2: block scan of cnt (+dis) ----------------
__global__ __launch_bounds__(SCAN_B) void k_scan1(int N) {
    __shared__ int s[SCAN_B];
    int t = threadIdx.x;
    int i = blockIdx.x * SCAN_B + t;
    int val = (i < N) ? g_cnt[i] : 0;
    s[t] = val;
    __syncthreads();
#pragma unroll
    for (int off = 1; off < SCAN_B; off <<= 1) {
        int x = (t >= off) ? s[t - off] : 0;
        __syncthreads();
        s[t] += x;
        __syncthreads();
    }
    if (i < N) {
        g_rowptr[i] = s[t] - val;          // exclusive within block
        float d = (float)val;
        g_dis[i] = (d > 0.f) ? rsqrtf(d) : 0.f;
    }
    if (t == SCAN_B - 1) g_blocksum[blockIdx.x] = s[t];
}

// ---------------- K3: finish scan (each block redundantly scans blocksums) ----
__global__ __launch_bounds__(256) void k_scan23(int N, int nb) {
    __shared__ int s[MAXNB];
    __shared__ int sx[MAXNB + 1];
    int t = threadIdx.x;
    int val = (t < nb) ? g_blocksum[t] : 0;
    s[t] = val;
    __syncthreads();
#pragma unroll
    for (int off = 1; off < MAXNB; off <<= 1) {
        int x = (t >= off) ? s[t - off] : 0;
        __syncthreads();
        s[t] += x;
        __syncthreads();
    }
    sx[t] = s[t] - val;
    if (t == MAXNB - 1) sx[MAXNB] = s[t];
    __syncthreads();

    int i = blockIdx.x * 256 + t;
    if (i < N) {
        int v = g_rowptr[i] + sx[i / SCAN_B];
        g_rowptr[i] = v;
        g_cursor[i] = v;
    }
    if (blockIdx.x == 0 && t == 0) g_rowptr[N] = sx[MAXNB];
}

// ---------------- K5: aggregation layer 1 (fp32 gather, weight from perm2) ----
// warp per node; 2 groups of 16 lanes (one edge each); 16 float4 chunks.
__global__ __launch_bounds__(256) void agg1_kernel(int N) {
    int wid = threadIdx.x >> 5;
    int lane = threadIdx.x & 31;
    int node = blockIdx.x * 8 + wid;
    if (node >= N) return;

    int start = g_rowptr[node];
    int end   = g_rowptr[node + 1];
    int half = lane >> 4;
    int ch   = lane & 15;

    const float4* h = (const float4*)g_h1;
    float4 acc = make_float4(0.f, 0.f, 0.f, 0.f);

    for (int k = start + half; k < end; k += 2) {
        int2 p = __ldg(&g_perm2[k]);
        float w = __int_as_float(p.y);
        float4 v = __ldg(&h[(size_t)p.x * 16 + ch]);
        acc.x = fmaf(w, v.x, acc.x);
        acc.y = fmaf(w, v.y, acc.y);
        acc.z = fmaf(w, v.z, acc.z);
        acc.w = fmaf(w, v.w, acc.w);
    }
    acc.x += __shfl_down_sync(0xffffffffu, acc.x, 16);
    acc.y += __shfl_down_sync(0xffffffffu, acc.y, 16);
    acc.z += __shfl_down_sync(0xffffffffu, acc.z, 16);
    acc.w += __shfl_down_sync(0xffffffffu, acc.w, 16);

    if (lane < 16) {
        float di = g_dis[node];
        acc.x *= di; acc.y *= di; acc.z *= di; acc.w *= di;
        ((float4*)g_agg1)[(size_t)node * 16 + ch] = acc;
    }
}

// ---------------- K6: GEMM2  h3 = dis .* (relu(agg1+b1) @ W2^T) --------------
// 320 thr: tx=tid%10 -> cols 4tx..4tx+3; ty=tid/10 (0..31) -> rowpairs 2ty,2ty+1.
__global__ __launch_bounds__(320) void gemm2_kernel(const float* __restrict__ W2,
                                                    const float* __restrict__ b1, int N) {
    __shared__ float2 xs2[32][65];
    __shared__ float2 wd[32][41];

    int tid = threadIdx.x;
    int tx = tid % 10;
    int ty = tid / 10;
    int rbase = blockIdx.x * 128;

    unsigned long long acc[2][4];
#pragma unroll
    for (int r = 0; r < 2; r++)
#pragma unroll
        for (int c = 0; c < 4; c++) acc[r][c] = 0ull;

#pragma unroll 1
    for (int kp = 0; kp < 2; kp++) {
        __syncthreads();
        for (int idx = tid; idx < 128 * 32; idx += 320) {
            int rr = idx >> 5, kk = idx & 31;
            int gr = rbase + rr;
            float v = 0.f;
            if (gr < N)
                v = fmaxf(g_agg1[(size_t)gr * F_HID + kp * 32 + kk] + b1[kp * 32 + kk], 0.f);
            ((float*)&xs2[kk][rr >> 1])[rr & 1] = v;
        }
        for (int idx = tid; idx < F_OUT * 32; idx += 320) {
            int j = idx >> 5, kk = idx & 31;
            float v = W2[j * F_HID + kp * 32 + kk];
            wd[kk][j] = make_float2(v, v);
        }
        __syncthreads();

#pragma unroll
        for (int kk = 0; kk < 32; kk++) {
            unsigned long long xp[2], wv[4];
#pragma unroll
            for (int r = 0; r < 2; r++)
                xp[r] = *(const unsigned long long*)&xs2[kk][2 * ty + r];
#pragma unroll
            for (int c = 0; c < 4; c++)
                wv[c] = *(const unsigned long long*)&wd[kk][4 * tx + c];
#pragma unroll
            for (int r = 0; r < 2; r++)
#pragma unroll
                for (int c = 0; c < 4; c++) ffma2(acc[r][c], xp[r], wv[c]);
        }
    }

#pragma unroll
    for (int r = 0; r < 2; r++) {
        int row0 = rbase + 2 * (2 * ty + r);
        if (row0 >= N) break;
        float d0 = g_dis[row0];
        float d1 = (row0 + 1 < N) ? g_dis[row0 + 1] : 0.f;
        float lo[4], hi[4];
#pragma unroll
        for (int c = 0; c < 4; c++) unpack2(acc[r][c], lo[c], hi[c]);
        *(float4*)&g_h3[(size_t)row0 * F_OUT + 4 * tx] =
            make_float4(lo[0] * d0, lo[1] * d0, lo[2] * d0, lo[3] * d0);
        if (row0 + 1 < N)
            *(float4*)&g_h3[(size_t)(row0 + 1) * F_OUT + 4 * tx] =
                make_float4(hi[0] * d1, hi[1] * d1, hi[2] * d1, hi[3] * d1);
    }
}

// ---------------- K7: aggregation layer 2 + b2 -> out ------------------------
// warp per node; 3 groups of 10 lanes; 10 float4 chunks; lanes 30,31 idle.
// Also re-zeros g_cnt for the next graph replay.
__global__ __launch_bounds__(256) void agg2_kernel(float* __restrict__ out,
                                                   const float* __restrict__ b2, int N) {
    int gi = blockIdx.x * 256 + threadIdx.x;
    if (gi < N) g_cnt[gi] = 0;           // prep next replay (zero-init covers call 1)

    int wid = threadIdx.x >> 5;
    int lane = threadIdx.x & 31;
    int node = blockIdx.x * 8 + wid;
    if (node >= N) return;

    int start = g_rowptr[node];
    int end   = g_rowptr[node + 1];
    int grp = lane / 10;
    int ch  = lane - grp * 10;

    const float4* h = (const float4*)g_h3;
    float4 acc = make_float4(0.f, 0.f, 0.f, 0.f);

    if (grp < 3) {
        for (int k = start + grp; k < end; k += 3) {
            int r = __ldg(&g_perm2[k]).x;
            float4 v = __ldg(&h[(size_t)r * 10 + ch]);
            acc.x += v.x; acc.y += v.y; acc.z += v.z; acc.w += v.w;
        }
    }
    acc.x += __shfl_down_sync(0xffffffffu, acc.x, 10) + __shfl_down_sync(0xffffffffu, acc.x, 20);
    acc.y += __shfl_down_sync(0xffffffffu, acc.y, 10) + __shfl_down_sync(0xffffffffu, acc.y, 20);
    acc.z += __shfl_down_sync(0xffffffffu, acc.z, 10) + __shfl_down_sync(0xffffffffu, acc.z, 20);
    acc.w += __shfl_down_sync(0xffffffffu, acc.w, 10) + __shfl_down_sync(0xffffffffu, acc.w, 20);

    if (lane < 10) {
        float di = g_dis[node];
        float4 bb = __ldg(&((const float4*)b2)[ch]);
        acc.x = fmaf(acc.x, di, bb.x);
        acc.y = fmaf(acc.y, di, bb.y);
        acc.z = fmaf(acc.z, di, bb.z);
        acc.w = fmaf(acc.w, di, bb.w);
        ((float4*)out)[(size_t)node * 10 + ch] = acc;
    }
}

// ---------------- launch ----------------
extern "C" void kernel_launch(void* const* d_in, const int* in_sizes, int n_in,
                              void* d_out, int out_size) {
    const float* x = nullptr; const int* ei = nullptr;
    const float* W1 = nullptr; const float* b1 = nullptr;
    const float* W2 = nullptr; const float* b2 = nullptr;
    int x_sz = 0, ei_sz = 0;

    for (int i = 0; i < n_in; i++) {
        int s = in_sizes[i];
        if (s == 8192)       W1 = (const float*)d_in[i];
        else if (s == 2560)  W2 = (const float*)d_in[i];
        else if (s == 64)    b1 = (const float*)d_in[i];
        else if (s == 40)    b2 = (const float*)d_in[i];
        else if (s == 12800000) { x = (const float*)d_in[i]; x_sz = s; }
        else if (s == 3200000)  { ei = (const int*)d_in[i]; ei_sz = s; }
    }
    if (!x || !ei || !W1 || !b1 || !W2 || !b2) {
        x  = (const float*)d_in[0];  x_sz  = in_sizes[0];
        ei = (const int*)d_in[1];    ei_sz = in_sizes[1];
        W1 = (const float*)d_in[2];
        b1 = (const float*)d_in[3];
        W2 = (const float*)d_in[4];
        b2 = (const float*)d_in[5];
    }

    float* out = (float*)d_out;
    int N = x_sz / F_IN;
    int E = ei_sz / 2;
    if (N > MAXN) N = MAXN;
    if (E > MAXE) E = MAXE;
    int nb = (N + SCAN_B - 1) / SCAN_B;

    int totalRB = (N + 127) / 128;
    int rbA = (totalRB + 1) / 2;
    int rbB = totalRB - rbA;
    int vecOK = ((E & 3) == 0) ? 1 : 0;
    int eBlocks = vecOK ? ((E / 4) + 255) / 256 : (E + 255) / 256;

    // [gemm1 first half || degree count] -> scans -> [gemm1 second half || CSR fill]
    gemm1_fused<<<rbA + eBlocks, 256>>>(x, W1, N, 0,   rbA, ei, E, 0, vecOK);
    k_scan1    <<<nb, SCAN_B>>>(N);
    k_scan23   <<<(N + 255) / 256, 256>>>(N, nb);
    gemm1_fused<<<rbB + eBlocks, 256>>>(x, W1, N, rbA, rbB, ei, E, 1, vecOK);

    agg1_kernel <<<(N + 7) / 8, 256>>>(N);
    gemm2_kernel<<<totalRB, 320>>>(W2, b1, N);
    agg2_kernel <<<(N + 7) / 8, 256>>>(out, b2, N);
}